// round 17
// baseline (speedup 1.0000x reference)
#include <cuda_runtime.h>
#include <cuda_fp16.h>
#include <math.h>
#include <stdint.h>

// Problem constants
#define S_LEN   2048
#define D_MODEL 1024
#define NH      16
#define NKV     4
#define HDIM    64
#define BATCH   2

// Scratch (device globals — no allocation allowed). All fp16.
__device__ __half g_xh[(size_t)BATCH * S_LEN * D_MODEL];   // X converted to fp16
__device__ __half g_q[(size_t)BATCH * NH  * S_LEN * HDIM]; // (b,h,s,d) roped, pre-scaled
__device__ __half g_k[(size_t)BATCH * NKV * S_LEN * HDIM]; // (b,kvh,s,d) roped
__device__ __half g_v[(size_t)BATCH * NKV * S_LEN * HDIM];
__device__ __half g_o[(size_t)BATCH * S_LEN * D_MODEL];    // (b,s,h*64+d)
__device__ float2 g_rope[(size_t)S_LEN * 512];             // [s][p] = (cos, sin)
__device__ __half g_wt [(size_t)1536 * 1024];              // [n][k] = (Wq|Wk|Wv)^T
__device__ __half g_wto[(size_t)1024 * 1024];              // Wo^T

// ---------------------------------------------------------------------------
// Helpers
// ---------------------------------------------------------------------------
__device__ __forceinline__ void mmah(float* d, const unsigned* a, const unsigned* b) {
    asm volatile(
        "mma.sync.aligned.m16n8k16.row.col.f32.f16.f16.f32 "
        "{%0,%1,%2,%3}, {%4,%5,%6,%7}, {%8,%9}, {%0,%1,%2,%3};"
        : "+f"(d[0]), "+f"(d[1]), "+f"(d[2]), "+f"(d[3])
        : "r"(a[0]), "r"(a[1]), "r"(a[2]), "r"(a[3]),
          "r"(b[0]), "r"(b[1]));
}
__device__ __forceinline__ unsigned fh2(float lo, float hi) {
    __half2 h = __floats2half2_rn(lo, hi);
    return *(unsigned*)&h;
}
__device__ __forceinline__ unsigned h2exp2u(unsigned x) {
    unsigned r;
    asm("ex2.approx.f16x2 %0, %1;" : "=r"(r) : "r"(x));
    return r;
}
__device__ __forceinline__ uint32_t smem_u32(const void* p) {
    uint32_t a;
    asm("{ .reg .u64 t; cvta.to.shared.u64 t, %1; cvt.u32.u64 %0, t; }"
        : "=r"(a) : "l"(p));
    return a;
}
__device__ __forceinline__ void ldsm4(
    unsigned& r0, unsigned& r1, unsigned& r2, unsigned& r3, uint32_t a) {
    asm volatile("ldmatrix.sync.aligned.m8n8.x4.shared.b16 {%0,%1,%2,%3}, [%4];"
        : "=r"(r0), "=r"(r1), "=r"(r2), "=r"(r3) : "r"(a));
}
__device__ __forceinline__ void ldsm4t(
    unsigned& r0, unsigned& r1, unsigned& r2, unsigned& r3, uint32_t a) {
    asm volatile("ldmatrix.sync.aligned.m8n8.x4.trans.shared.b16 {%0,%1,%2,%3}, [%4];"
        : "=r"(r0), "=r"(r1), "=r"(r2), "=r"(r3) : "r"(a));
}
__device__ __forceinline__ void cpa16(uint32_t dst, const void* src) {
    asm volatile("cp.async.cg.shared.global [%0], [%1], 16;"
                 :: "r"(dst), "l"(src) : "memory");
}
#define CPA_COMMIT() asm volatile("cp.async.commit_group;" ::: "memory")
#define CPA_WAIT0()  asm volatile("cp.async.wait_group 0;" ::: "memory")
#define CPA_WAIT1()  asm volatile("cp.async.wait_group 1;" ::: "memory")

// ---------------------------------------------------------------------------
// Fused prep: rope table + 4 weight transposes + X fp16 conversion.
// ---------------------------------------------------------------------------
__device__ __forceinline__ void do_transpose(
    const float* __restrict__ src, int cols, __half* dst,
    int bx, int by, int tx, int ty, float (*tile)[33])
{
#pragma unroll
    for (int i = 0; i < 32; i += 8)
        tile[ty + i][tx] = src[(size_t)(by + ty + i) * cols + bx + tx];
    __syncthreads();
#pragma unroll
    for (int i = 0; i < 32; i += 8)
        dst[(size_t)(bx + ty + i) * 1024 + by + tx] = __float2half_rn(tile[tx][ty + i]);
}

__global__ __launch_bounds__(256) void prep_kernel(
    const float* __restrict__ X,
    const float* __restrict__ Wq, const float* __restrict__ Wk,
    const float* __restrict__ Wv, const float* __restrict__ Wo)
{
    __shared__ float tile[32][33];
    const int blk = blockIdx.x;
    const int tid = threadIdx.x;

    if (blk < 4096) {
        int idx = blk * 256 + tid;
        int s = idx >> 9, p = idx & 511;
        const double CL2 = 9.210340371976184 / 512.0;
        double inv = exp(-(double)p * CL2);
        double ang = (double)s * inv;
        const double TWO_PI = 6.283185307179586476925;
        double r = ang - TWO_PI * rint(ang * (1.0 / TWO_PI));
        float sf, cf;
        __sincosf((float)r, &sf, &cf);
        g_rope[idx] = make_float2(cf, sf);
        return;
    }
    if (blk >= 6656) {
        size_t base = (size_t)(blk - 6656) * 2048 + tid * 8;
        float4 v0 = *(const float4*)(X + base);
        float4 v1 = *(const float4*)(X + base + 4);
        uint4 u = { fh2(v0.x, v0.y), fh2(v0.z, v0.w),
                    fh2(v1.x, v1.y), fh2(v1.z, v1.w) };
        *(uint4*)(g_xh + base) = u;
        return;
    }

    const int tx = tid & 31, ty = tid >> 5;
    if (blk < 5120) {
        int r = blk - 4096;
        do_transpose(Wq, 1024, g_wt, (r & 31) * 32, (r >> 5) * 32, tx, ty, tile);
    } else if (blk < 5376) {
        int r = blk - 5120;
        do_transpose(Wk, 256, g_wt + (size_t)1024 * 1024, (r & 7) * 32, (r >> 3) * 32, tx, ty, tile);
    } else if (blk < 5632) {
        int r = blk - 5376;
        do_transpose(Wv, 256, g_wt + (size_t)1280 * 1024, (r & 7) * 32, (r >> 3) * 32, tx, ty, tile);
    } else {
        int r = blk - 5632;
        do_transpose(Wo, 1024, g_wto, (r & 31) * 32, (r >> 5) * 32, tx, ty, tile);
    }
}

// ---------------------------------------------------------------------------
// GEMM geometry: 128x128 CTA, BK=32 halves, 4 warps (2x2), warp tile 64x64.
// 128 threads/CTA, 2 CTAs/SM. Smem rows 40 halves; 3-stage cp.async.
// ---------------------------------------------------------------------------
#define HR2 40
#define GST (128 * HR2)
#define GEMM_SMEM_BYTES (3 * 2 * GST * 2)   // 61440

#define QSCALE 0.04508422f   // (1/32) * log2(e)

__global__ __launch_bounds__(128, 2) void qkv_gemm()
{
    extern __shared__ __half gsm[];
    __half* Ash = gsm;                  // [3][GST]
    __half* Bsh = gsm + 3 * GST;        // [3][GST]

    const int tid  = threadIdx.x;
    const int lane = tid & 31, warp = tid >> 5;
    const int g = lane >> 2, t = lane & 3;
    const int l7 = lane & 7, lm = (lane >> 3) & 1, lh = (lane >> 4) & 1;
    const int wm = (warp >> 1) * 64, wn = (warp & 1) * 64;
    const int bn = blockIdx.x * 128, bm = blockIdx.y * 128;
    const int kind = (bn < 1024) ? 0 : (bn < 1280) ? 1 : 2;

    // fill: 512 chunks of 8 halves per matrix per stage; 4/thread/matrix
    const int f_r = tid >> 2, f_c = (tid & 3) * 8;   // rows f_r + 32i
    const __half* ApG[4];
    const __half* BpG[4];
    uint32_t so[4];
#pragma unroll
    for (int i = 0; i < 4; ++i) {
        int r = f_r + 32 * i;
        ApG[i] = g_xh + (size_t)(bm + r) * 1024 + f_c;
        BpG[i] = g_wt + (size_t)(bn + r) * 1024 + f_c;
        so[i] = (r * HR2 + f_c) * 2;
    }
    const uint32_t ash = smem_u32(Ash), bsh = smem_u32(Bsh);

    float acc[4][8][4];
#pragma unroll
    for (int mi = 0; mi < 4; ++mi)
#pragma unroll
        for (int ni = 0; ni < 8; ++ni)
#pragma unroll
            for (int c = 0; c < 4; ++c) acc[mi][ni][c] = 0.f;

    // prologue: tiles 0,1
#pragma unroll
    for (int pt = 0; pt < 2; ++pt) {
        uint32_t sb = pt * GST * 2;
#pragma unroll
        for (int i = 0; i < 4; ++i) {
            cpa16(ash + sb + so[i], ApG[i] + pt * 32);
            cpa16(bsh + sb + so[i], BpG[i] + pt * 32);
        }
        CPA_COMMIT();
    }
    CPA_WAIT1();
    __syncthreads();

    for (int kt = 0; kt < 32; ++kt) {
        const int cur = kt % 3;
        if (kt + 2 < 32) {
            int ko = (kt + 2) * 32;
            uint32_t sb = ((kt + 2) % 3) * GST * 2;
#pragma unroll
            for (int i = 0; i < 4; ++i) {
                cpa16(ash + sb + so[i], ApG[i] + ko);
                cpa16(bsh + sb + so[i], BpG[i] + ko);
            }
            CPA_COMMIT();
        }

        const uint32_t ab = ash + cur * GST * 2;
        const uint32_t bb = bsh + cur * GST * 2;
#pragma unroll
        for (int ks = 0; ks < 2; ++ks) {
            unsigned a[4][4], b[8][2];
#pragma unroll
            for (int mi = 0; mi < 4; ++mi)
                ldsm4(a[mi][0], a[mi][1], a[mi][2], a[mi][3],
                      ab + (wm + mi * 16 + lm * 8 + l7) * 80 + ks * 32 + lh * 16);
#pragma unroll
            for (int p = 0; p < 4; ++p) {
                unsigned r0, r1, r2, r3;
                ldsm4(r0, r1, r2, r3,
                      bb + (wn + (2 * p + lh) * 8 + l7) * 80 + ks * 32 + lm * 16);
                b[2 * p][0] = r0; b[2 * p][1] = r1;
                b[2 * p + 1][0] = r2; b[2 * p + 1][1] = r3;
            }
#pragma unroll
            for (int mi = 0; mi < 4; ++mi)
#pragma unroll
                for (int ni = 0; ni < 8; ++ni)
                    mmah(acc[mi][ni], a[mi], b[ni]);
        }

        if (kt < 30) CPA_WAIT1();
        else if (kt == 30) CPA_WAIT0();
        if (kt < 31) __syncthreads();
    }

    // Epilogue: RoPE via table + scatter (fp16 stores). Q pre-scaled.
#pragma unroll
    for (int mi = 0; mi < 4; ++mi) {
#pragma unroll
        for (int ni = 0; ni < 8; ++ni) {
            int n = bn + wn + ni * 8 + 2 * t;
#pragma unroll
            for (int half_ = 0; half_ < 2; ++half_) {
                int m = bm + wm + mi * 16 + g + half_ * 8;
                int b_ = m >> 11, s = m & 2047;
                float c0 = acc[mi][ni][half_ * 2 + 0];
                float c1 = acc[mi][ni][half_ * 2 + 1];
                if (kind == 0) {
                    float2 cs = g_rope[(size_t)s * 512 + (n >> 1)];
                    int h = n >> 6, d = n & 63;
                    *(__half2*)(g_q + (((size_t)b_ * NH + h) * S_LEN + s) * HDIM + d) =
                        __floats2half2_rn((c0 * cs.x - c1 * cs.y) * QSCALE,
                                          (c0 * cs.y + c1 * cs.x) * QSCALE);
                } else if (kind == 1) {
                    int np = n - 1024, kvh = np >> 6, d = np & 63;
                    float2 cs = g_rope[(size_t)s * 512 + (d >> 1)];
                    *(__half2*)(g_k + (((size_t)b_ * NKV + kvh) * S_LEN + s) * HDIM + d) =
                        __floats2half2_rn(c0 * cs.x - c1 * cs.y, c0 * cs.y + c1 * cs.x);
                } else {
                    int np = n - 1280, kvh = np >> 6, d = np & 63;
                    *(__half2*)(g_v + (((size_t)b_ * NKV + kvh) * S_LEN + s) * HDIM + d) =
                        __floats2half2_rn(c0, c1);
                }
            }
        }
    }
}

// ---------------------------------------------------------------------------
// Flash attention: 128-thread CTA, 4 warps x 32 q-rows, 2 CTAs/SM.
// Q fragments hoisted to registers. fp16x2 softmax feeding PV directly.
// ---------------------------------------------------------------------------
#define FH 72
#define KV_H (64 * FH)
#define FA_HALVES (128 * FH + 2 * KV_H + 2 * KV_H)
#define FA_BYTES (FA_HALVES * 2)       // 55296

__global__ __launch_bounds__(128, 2) void flash_kernel()
{
    extern __shared__ __half fsm[];
    __half* Qs = fsm;                  // [128][72]
    __half* Ks = fsm + 128 * FH;       // [2][64][72]
    __half* Vs = Ks + 2 * KV_H;        // [2][64][72]

    const int tid  = threadIdx.x;
    const int lane = tid & 31, warp = tid >> 5;
    const int g = lane >> 2, t = lane & 3;
    const int l7 = lane & 7, lm = (lane >> 3) & 1, lh = (lane >> 4) & 1;
    const int qt = blockIdx.x, h = blockIdx.y, b = blockIdx.z;
    const int kvh = h >> 2;
    const int wrow = warp * 32;

    const __half* Qg = g_q + (((size_t)b * NH  + h  ) * S_LEN + qt * 128) * HDIM;
    const __half* Kg = g_k + (((size_t)b * NKV + kvh) * S_LEN) * HDIM;
    const __half* Vg = g_v + (((size_t)b * NKV + kvh) * S_LEN) * HDIM;

    const uint32_t qs_b = smem_u32(Qs);
    const uint32_t ks_b = smem_u32(Ks);
    const uint32_t vs_b = smem_u32(Vs);

#pragma unroll
    for (int p = 0; p < 8; ++p) {
        int f = tid + p * 128;
        int r = f >> 3, c8 = (f & 7) << 3;
        cpa16(qs_b + (r * FH + c8) * 2, Qg + (size_t)r * HDIM + c8);
    }
#pragma unroll
    for (int i = 0; i < 4; ++i) {
        int f = tid + i * 128;
        int kv = f >> 3, c8 = (f & 7) << 3;
        cpa16(ks_b + (kv * FH + c8) * 2, Kg + (size_t)kv * HDIM + c8);
        cpa16(vs_b + (kv * FH + c8) * 2, Vg + (size_t)kv * HDIM + c8);
    }
    CPA_COMMIT();
    CPA_WAIT0();
    __syncthreads();

    // Hoist Q fragments (tile-invariant) into registers
    unsigned qa[4][2][4];
#pragma unroll
    for (int kk = 0; kk < 4; ++kk)
#pragma unroll
        for (int mi = 0; mi < 2; ++mi)
            ldsm4(qa[kk][mi][0], qa[kk][mi][1], qa[kk][mi][2], qa[kk][mi][3],
                  qs_b + (wrow + mi * 16 + lm * 8 + l7) * 144 + kk * 32 + lh * 16);

    float o[2][8][4];
#pragma unroll
    for (int mi = 0; mi < 2; ++mi)
#pragma unroll
        for (int j = 0; j < 8; ++j)
#pragma unroll
            for (int c = 0; c < 4; ++c) o[mi][j][c] = 0.f;
    float mx[4] = {-INFINITY, -INFINITY, -INFINITY, -INFINITY};
    float lx[4] = {0.f, 0.f, 0.f, 0.f};
    const unsigned FULL = 0xffffffffu;

    for (int kt = 0; kt < 32; ++kt) {
        const int cur = kt & 1;
        const uint32_t kc_b = ks_b + cur * KV_H * 2;
        const uint32_t vc_b = vs_b + cur * KV_H * 2;

        if (kt < 31) {
            const int nxt = cur ^ 1;
            const __half* Kt = Kg + (size_t)(kt + 1) * 64 * HDIM;
            const __half* Vt = Vg + (size_t)(kt + 1) * 64 * HDIM;
            const uint32_t kn_b = ks_b + nxt * KV_H * 2;
            const uint32_t vn_b = vs_b + nxt * KV_H * 2;
#pragma unroll
            for (int i = 0; i < 4; ++i) {
                int f = tid + i * 128;
                int kv = f >> 3, c8 = (f & 7) << 3;
                cpa16(kn_b + (kv * FH + c8) * 2, Kt + (size_t)kv * HDIM + c8);
                cpa16(vn_b + (kv * FH + c8) * 2, Vt + (size_t)kv * HDIM + c8);
            }
            CPA_COMMIT();
        }

        // S = Q K^T (log2-domain; Q pre-scaled): 32 x 64 per warp
        float s[2][8][4];
#pragma unroll
        for (int mi = 0; mi < 2; ++mi)
#pragma unroll
            for (int j = 0; j < 8; ++j)
#pragma unroll
                for (int c = 0; c < 4; ++c) s[mi][j][c] = 0.f;

#pragma unroll
        for (int kk = 0; kk < 4; ++kk) {
#pragma unroll
            for (int p = 0; p < 4; ++p) {
                unsigned r0, r1, r2, r3;
                ldsm4(r0, r1, r2, r3,
                      kc_b + ((2 * p + lh) * 8 + l7) * 144 + kk * 32 + lm * 16);
                unsigned b0[2] = { r0, r1 }, b1[2] = { r2, r3 };
                mmah(s[0][2 * p],     qa[kk][0], b0);
                mmah(s[1][2 * p],     qa[kk][1], b0);
                mmah(s[0][2 * p + 1], qa[kk][0], b1);
                mmah(s[1][2 * p + 1], qa[kk][1], b1);
            }
        }

        // Online softmax, all fp16x2 (log2 domain; Q pre-scaled)
        float cf[4];
        unsigned eh[2][8][2];
#pragma unroll
        for (int mi = 0; mi < 2; ++mi) {
            __half2 ph0[8], ph1[8];
#pragma unroll
            for (int j = 0; j < 8; ++j) {
                unsigned u0 = fh2(s[mi][j][0], s[mi][j][1]);
                unsigned u1 = fh2(s[mi][j][2], s[mi][j][3]);
                ph0[j] = *(__half2*)&u0;
                ph1[j] = *(__half2*)&u1;
            }
            __half2 m0 = ph0[0], m1 = ph1[0];
#pragma unroll
            for (int j = 1; j < 8; ++j) {
                m0 = __hmax2(m0, ph0[j]);
                m1 = __hmax2(m1, ph1[j]);
            }
            float rm0 = fmaxf(__low2float(m0), __high2float(m0));
            float rm1 = fmaxf(__low2float(m1), __high2float(m1));
#pragma unroll
            for (int off = 1; off <= 2; off <<= 1) {
                rm0 = fmaxf(rm0, __shfl_xor_sync(FULL, rm0, off));
                rm1 = fmaxf(rm1, __shfl_xor_sync(FULL, rm1, off));
            }
            float nm0 = fmaxf(mx[2 * mi + 0], rm0);
            float nm1 = fmaxf(mx[2 * mi + 1], rm1);
            cf[2 * mi + 0] = exp2f(mx[2 * mi + 0] - nm0);
            cf[2 * mi + 1] = exp2f(mx[2 * mi + 1] - nm1);

            __half2 nh0 = __float2half2_rn(nm0);
            __half2 nh1 = __float2half2_rn(nm1);
            __half2 hs0 = __float2half2_rn(0.f), hs1 = hs0;
#pragma unroll
            for (int j = 0; j < 8; ++j) {
                __half2 d0 = __hsub2(ph0[j], nh0);
                __half2 d1 = __hsub2(ph1[j], nh1);
                unsigned e0 = h2exp2u(*(unsigned*)&d0);
                unsigned e1 = h2exp2u(*(unsigned*)&d1);
                eh[mi][j][0] = e0;
                eh[mi][j][1] = e1;
                hs0 = __hadd2(hs0, *(__half2*)&e0);
                hs1 = __hadd2(hs1, *(__half2*)&e1);
            }
            float2 f0 = __half22float2(hs0);
            float2 f1 = __half22float2(hs1);
            float rs0 = f0.x + f0.y, rs1 = f1.x + f1.y;
#pragma unroll
            for (int off = 1; off <= 2; off <<= 1) {
                rs0 += __shfl_xor_sync(FULL, rs0, off);
                rs1 += __shfl_xor_sync(FULL, rs1, off);
            }
            lx[2 * mi + 0] = lx[2 * mi + 0] * cf[2 * mi + 0] + rs0;
            lx[2 * mi + 1] = lx[2 * mi + 1] * cf[2 * mi + 1] + rs1;
            mx[2 * mi + 0] = nm0;
            mx[2 * mi + 1] = nm1;
        }

        // Rescale O only if some row's max moved (exp2f(0)==1 exactly)
        bool nochg = (cf[0] == 1.f) & (cf[1] == 1.f) & (cf[2] == 1.f) & (cf[3] == 1.f);
        if (!__all_sync(FULL, nochg)) {
#pragma unroll
            for (int mi = 0; mi < 2; ++mi)
#pragma unroll
                for (int jn = 0; jn < 8; ++jn) {
                    o[mi][jn][0] *= cf[2 * mi + 0]; o[mi][jn][1] *= cf[2 * mi + 0];
                    o[mi][jn][2] *= cf[2 * mi + 1]; o[mi][jn][3] *= cf[2 * mi + 1];
                }
        }

        // O += P V ; aP = eh directly, V via ldmatrix.trans (shared across mi)
#pragma unroll
        for (int kk = 0; kk < 4; ++kk) {
            unsigned aP[2][4];
#pragma unroll
            for (int mi = 0; mi < 2; ++mi) {
                aP[mi][0] = eh[mi][2 * kk][0];
                aP[mi][1] = eh[mi][2 * kk][1];
                aP[mi][2] = eh[mi][2 * kk + 1][0];
                aP[mi][3] = eh[mi][2 * kk + 1][1];
            }
#pragma unroll
            for (int p = 0; p < 4; ++p) {
                unsigned r0, r1, r2, r3;
                ldsm4t(r0, r1, r2, r3,
                       vc_b + (kk * 16 + lm * 8 + l7) * 144 + (2 * p + lh) * 16);
                unsigned b0[2] = { r0, r1 }, b1[2] = { r2, r3 };
                mmah(o[0][2 * p],     aP[0], b0);
                mmah(o[1][2 * p],     aP[1], b0);
                mmah(o[0][2 * p + 1], aP[0], b1);
                mmah(o[1][2 * p + 1], aP[1], b1);
            }
        }

        if (kt < 31) {
            CPA_WAIT0();
            __syncthreads();
        }
    }

    // Normalize + write (b,s,D) as fp16
#pragma unroll
    for (int mi = 0; mi < 2; ++mi) {
        float inv0 = 1.f / lx[2 * mi + 0], inv1 = 1.f / lx[2 * mi + 1];
        int r0 = qt * 128 + wrow + mi * 16 + g, r1 = r0 + 8;
#pragma unroll
        for (int jn = 0; jn < 8; ++jn) {
            int col = h * HDIM + jn * 8 + 2 * t;
            *(__half2*)&g_o[((size_t)b * S_LEN + r0) * D_MODEL + col] =
                __floats2half2_rn(o[mi][jn][0] * inv0, o[mi][jn][1] * inv0);
            *(__half2*)&g_o[((size_t)b * S_LEN + r1) * D_MODEL + col] =
                __floats2half2_rn(o[mi][jn][2] * inv1, o[mi][jn][3] * inv1);
        }
    }
}

// ---------------------------------------------------------------------------
// Output projection: g_o @ Wo^T -> out fp32. 64x64 warp tiles, 128 threads.
// ---------------------------------------------------------------------------
__global__ __launch_bounds__(128, 2) void out_gemm(float* __restrict__ out)
{
    extern __shared__ __half gsm[];
    __half* Ash = gsm;
    __half* Bsh = gsm + 3 * GST;

    const int tid  = threadIdx.x;
    const int lane = tid & 31, warp = tid >> 5;
    const int g = lane >> 2, t = lane & 3;
    const int l7 = lane & 7, lm = (lane >> 3) & 1, lh = (lane >> 4) & 1;
    const int wm = (warp >> 1) * 64, wn = (warp & 1) * 64;
    const int bn = blockIdx.x * 128, bm = blockIdx.y * 128;

    const int f_r = tid >> 2, f_c = (tid & 3) * 8;
    const __half* ApG[4];
    const __half* BpG[4];
    uint32_t so[4];
#pragma unroll
    for (int i = 0; i < 4; ++i) {
        int r = f_r + 32 * i;
        ApG[i] = g_o   + (size_t)(bm + r) * 1024 + f_c;
        BpG[i] = g_wto + (size_t)(bn + r) * 1024 + f_c;
        so[i] = (r * HR2 + f_c) * 2;
    }
    const uint32_t ash = smem_u32(Ash), bsh = smem_u32(Bsh);

    float acc[4][8][4];
#pragma unroll
    for (int mi = 0; mi < 4; ++mi)
#pragma unroll
        for (int ni = 0; ni < 8; ++ni)
#pragma unroll
            for (int c = 0; c < 4; ++c) acc[mi][ni][c] = 0.f;

#pragma unroll
    for (int pt = 0; pt < 2; ++pt) {
        uint32_t sb = pt * GST * 2;
#pragma unroll
        for (int i = 0; i < 4; ++i) {
            cpa16(ash + sb + so[i], ApG[i] + pt * 32);
            cpa16(bsh + sb + so[i], BpG[i] + pt * 32);
        }
        CPA_COMMIT();
    }
    CPA_WAIT1();
    __syncthreads();

    for (int kt = 0; kt < 32; ++kt) {
        const int cur = kt % 3;
        if (kt + 2 < 32) {
            int ko = (kt + 2) * 32;
            uint32_t sb = ((kt + 2) % 3) * GST * 2;
#pragma unroll
            for (int i = 0; i < 4; ++i) {
                cpa16(ash + sb + so[i], ApG[i] + ko);
                cpa16(bsh + sb + so[i], BpG[i] + ko);
            }
            CPA_COMMIT();
        }

        const uint32_t ab = ash + cur * GST * 2;
        const uint32_t bb = bsh + cur * GST * 2;
#pragma unroll
        for (int ks = 0; ks < 2; ++ks) {
            unsigned a[4][4], b[8][2];
#pragma unroll
            for (int mi = 0; mi < 4; ++mi)
                ldsm4(a[mi][0], a[mi][1], a[mi][2], a[mi][3],
                      ab + (wm + mi * 16 + lm * 8 + l7) * 80 + ks * 32 + lh * 16);
#pragma unroll
            for (int p = 0; p < 4; ++p) {
                unsigned r0, r1, r2, r3;
                ldsm4(r0, r1, r2, r3,
                      bb + (wn + (2 * p + lh) * 8 + l7) * 80 + ks * 32 + lm * 16);
                b[2 * p][0] = r0; b[2 * p][1] = r1;
                b[2 * p + 1][0] = r2; b[2 * p + 1][1] = r3;
            }
#pragma unroll
            for (int mi = 0; mi < 4; ++mi)
#pragma unroll
                for (int ni = 0; ni < 8; ++ni)
                    mmah(acc[mi][ni], a[mi], b[ni]);
        }

        if (kt < 30) CPA_WAIT1();
        else if (kt == 30) CPA_WAIT0();
        if (kt < 31) __syncthreads();
    }

#pragma unroll
    for (int mi = 0; mi < 4; ++mi)
#pragma unroll
        for (int ni = 0; ni < 8; ++ni) {
            int n = bn + wn + ni * 8 + 2 * t;
#pragma unroll
            for (int half_ = 0; half_ < 2; ++half_) {
                int m = bm + wm + mi * 16 + g + half_ * 8;
                float2 r = { acc[mi][ni][half_ * 2 + 0], acc[mi][ni][half_ * 2 + 1] };
                *(float2*)&out[(size_t)m * 1024 + n] = r;
            }
        }
}

// ---------------------------------------------------------------------------
extern "C" void kernel_launch(void* const* d_in, const int* in_sizes, int n_in,
                              void* d_out, int out_size)
{
    const float* x  = (const float*)d_in[0];
    const float* Wq = (const float*)d_in[1];
    const float* Wk = (const float*)d_in[2];
    const float* Wv = (const float*)d_in[3];
    const float* Wo = (const float*)d_in[4];
    float* out = (float*)d_out;

    (void)in_sizes; (void)n_in; (void)out_size;

    cudaFuncSetAttribute(flash_kernel,
                         cudaFuncAttributeMaxDynamicSharedMemorySize, FA_BYTES);
    cudaFuncSetAttribute(qkv_gemm,
                         cudaFuncAttributeMaxDynamicSharedMemorySize, GEMM_SMEM_BYTES);
    cudaFuncSetAttribute(out_gemm,
                         cudaFuncAttributeMaxDynamicSharedMemorySize, GEMM_SMEM_BYTES);

    prep_kernel<<<8704, 256>>>(x, Wq, Wk, Wv, Wo);
    qkv_gemm<<<dim3(12, 32), 128, GEMM_SMEM_BYTES>>>();
    flash_kernel<<<dim3(16, 16, 2), 128, FA_BYTES>>>();
    out_gemm<<<dim3(8, 32), 128, GEMM_SMEM_BYTES>>>(out);
}